// round 14
// baseline (speedup 1.0000x reference)
#include <cuda_runtime.h>
#include <cuda_fp16.h>
#include <cstdint>

#define B_   8
#define D_   512
#define L_   4096
#define T_   8192
#define KS   17

// ---------------- device scratch ----------------
__device__ __half g_A[3][D_][D_];         // folded weights fp16 [k][e][c]
__device__ float  g_cb[D_];               // projected conv bias
__device__ __half g_z[(size_t)B_ * D_ * T_];   // intermediate (67 MB, fp16)

// ---------------- PTX helpers ----------------
__device__ __forceinline__ uint32_t smem_u32(const void* p) {
    uint32_t a;
    asm("{ .reg .u64 t; cvta.to.shared.u64 t, %1; cvt.u32.u64 %0, t; }" : "=r"(a) : "l"(p));
    return a;
}
__device__ __forceinline__ void cp16(uint32_t dst, const void* src) {
    asm volatile("cp.async.cg.shared.global [%0], [%1], 16;" :: "r"(dst), "l"(src));
}
__device__ __forceinline__ void cp16z(uint32_t dst, const void* src, int nbytes) {
    asm volatile("cp.async.cg.shared.global [%0], [%1], 16, %2;"
                 :: "r"(dst), "l"(src), "r"(nbytes));
}
#define CP_COMMIT()  asm volatile("cp.async.commit_group;" ::: "memory")
#define CP_WAIT0()   asm volatile("cp.async.wait_group 0;" ::: "memory")
#define CP_WAIT1()   asm volatile("cp.async.wait_group 1;" ::: "memory")

__device__ __forceinline__ void ldsm_x4(uint32_t* r, uint32_t addr) {
    asm volatile("ldmatrix.sync.aligned.m8n8.x4.shared.b16 {%0,%1,%2,%3}, [%4];"
                 : "=r"(r[0]), "=r"(r[1]), "=r"(r[2]), "=r"(r[3]) : "r"(addr));
}
__device__ __forceinline__ void ldsm_x4_t(uint32_t* r, uint32_t addr) {
    asm volatile("ldmatrix.sync.aligned.m8n8.x4.trans.shared.b16 {%0,%1,%2,%3}, [%4];"
                 : "=r"(r[0]), "=r"(r[1]), "=r"(r[2]), "=r"(r[3]) : "r"(addr));
}
__device__ __forceinline__ void ldsm_x2_t(uint32_t* r, uint32_t addr) {
    asm volatile("ldmatrix.sync.aligned.m8n8.x2.trans.shared.b16 {%0,%1}, [%2];"
                 : "=r"(r[0]), "=r"(r[1]) : "r"(addr));
}
__device__ __forceinline__ void mma_fp16(float* d, const uint32_t* a, const uint32_t* b) {
    asm volatile("mma.sync.aligned.m16n8k16.row.col.f32.f16.f16.f32 "
                 "{%0,%1,%2,%3}, {%4,%5,%6,%7}, {%8,%9}, {%0,%1,%2,%3};"
                 : "+f"(d[0]), "+f"(d[1]), "+f"(d[2]), "+f"(d[3])
                 : "r"(a[0]), "r"(a[1]), "r"(a[2]), "r"(a[3]), "r"(b[0]), "r"(b[1]));
}
__device__ __forceinline__ unsigned long long pack2(float lo, float hi) {
    unsigned long long r;
    asm("mov.b64 %0, {%1, %2};" : "=l"(r) : "f"(lo), "f"(hi));
    return r;
}
__device__ __forceinline__ unsigned long long fma2(unsigned long long a,
                                                   unsigned long long b,
                                                   unsigned long long c) {
    unsigned long long d;
    asm("fma.rn.f32x2 %0, %1, %2, %3;" : "=l"(d) : "l"(a), "l"(b), "l"(c));
    return d;
}
__device__ __forceinline__ float2 unpack2(unsigned long long v) {
    float2 f;
    asm("mov.b64 {%0, %1}, %2;" : "=f"(f.x), "=f"(f.y) : "l"(v));
    return f;
}

// ---------------- kernel 1: prep = single-shot-K HMMA fold | cb --------------
// fold[e][n] = sum_d P[e][d] W[d][n], n = c*3+k.  Tile 64e x 64n, FULL K=512
// resident in smem -> one bulk load + 32 unrolled HMMA k-steps per block.
#define FOLD_BLKS 192
#define PREP_GRID (FOLD_BLKS + 2)
#define FAR   1040                      // A row: 512 halfs (1024B) + 16B pad
#define FA_BYTES (64 * FAR)             // 66560
#define FBR   144                       // B row: 64 halfs + 16B pad
#define FB_BYTES (512 * FBR)            // 73728
#define PREP_SMEM (FA_BYTES + FB_BYTES) // 140288

__global__ __launch_bounds__(256) void prep_kernel(const float* __restrict__ conv_w,
                                                   const float* __restrict__ conv_b,
                                                   const float* __restrict__ proj_w) {
    extern __shared__ char psm[];
    const int bx = blockIdx.x;
    const int t  = threadIdx.x;

    if (bx < FOLD_BLKS) {
        const int e0 = (bx / 24) * 64;
        const int n0 = (bx % 24) * 64;
        const uint32_t sA = smem_u32(psm);
        const uint32_t sB = sA + FA_BYTES;
        __half* hA = (__half*)psm;
        __half* hB = (__half*)(psm + FA_BYTES);
        const int wid = t >> 5, lane = t & 31;
        const int e_w = (wid & 1) * 32;
        const int n_w = (wid >> 1) * 16;

        // A: 64 e-rows x 128 float4 (full K=512) -> fp16
#pragma unroll 4
        for (int p = 0; p < 32; p++) {
            int idx = p * 256 + t;
            int row = idx >> 7, q = idx & 127;
            float4 v = *(const float4*)(proj_w + (size_t)(e0 + row) * D_ + q * 4);
            __half2 h0 = __floats2half2_rn(v.x, v.y);
            __half2 h1 = __floats2half2_rn(v.z, v.w);
            uint2 u; u.x = *(uint32_t*)&h0; u.y = *(uint32_t*)&h1;
            *(uint2*)&hA[row * 520 + q * 4] = u;
        }
        // B: 512 d-rows x 16 float4 -> fp16
#pragma unroll 4
        for (int p = 0; p < 32; p++) {
            int idx = p * 256 + t;
            int row = idx >> 4, q = idx & 15;
            float4 v = *(const float4*)(conv_w + (size_t)row * (3 * D_) + n0 + q * 4);
            __half2 h0 = __floats2half2_rn(v.x, v.y);
            __half2 h1 = __floats2half2_rn(v.z, v.w);
            uint2 u; u.x = *(uint32_t*)&h0; u.y = *(uint32_t*)&h1;
            *(uint2*)&hB[row * 72 + q * 4] = u;
        }
        __syncthreads();

        float acc[2][2][4];
#pragma unroll
        for (int mt = 0; mt < 2; mt++)
#pragma unroll
            for (int nt = 0; nt < 2; nt++)
#pragma unroll
                for (int j = 0; j < 4; j++) acc[mt][nt][j] = 0.f;

        const uint32_t aRow = (uint32_t)(e_w + (lane & 15)) * FAR + (uint32_t)(lane >> 4) * 16;
        const uint32_t bOff = (uint32_t)((lane & 7) + ((lane >> 3) & 1) * 8) * FBR
                            + (uint32_t)(n_w + (lane >> 4) * 8) * 2;

#pragma unroll 8
        for (int kh = 0; kh < 32; ++kh) {
            uint32_t aF[2][4], bF[2][2];
#pragma unroll
            for (int mt = 0; mt < 2; mt++)
                ldsm_x4(aF[mt], sA + aRow + mt * (16 * FAR) + kh * 32);
            {
                uint32_t r[4];
                ldsm_x4_t(r, sB + bOff + (uint32_t)kh * 16 * FBR);
                bF[0][0] = r[0]; bF[0][1] = r[1]; bF[1][0] = r[2]; bF[1][1] = r[3];
            }
#pragma unroll
            for (int mt = 0; mt < 2; mt++)
#pragma unroll
                for (int nt = 0; nt < 2; nt++)
                    mma_fp16(acc[mt][nt], aF[mt], bF[nt]);
        }

        // scatter epilogue: D[e][n] -> g_A[n%3][e][n/3]
#pragma unroll
        for (int mt = 0; mt < 2; mt++) {
            int eb = e0 + e_w + mt * 16 + (lane >> 2);
#pragma unroll
            for (int nt = 0; nt < 2; nt++) {
                int nb = n0 + n_w + nt * 8 + (lane & 3) * 2;
#pragma unroll
                for (int j = 0; j < 4; j++) {
                    int e = eb + ((j >> 1) ? 8 : 0);
                    int n = nb + (j & 1);
                    g_A[n % 3][e][n / 3] = __float2half_rn(acc[mt][nt][j]);
                }
            }
        }
    } else {
        // ---- cb: warp per 32 e, coalesced reads + shfl reduce ----
        const int warp = t >> 5, lane = t & 31;
        const int ebase = (bx - FOLD_BLKS) * 256 + warp * 32;
#pragma unroll 4
        for (int eo = 0; eo < 32; eo++) {
            int e = ebase + eo;
            const float* row = proj_w + (size_t)e * D_;
            float s = 0.f;
#pragma unroll
            for (int d = lane; d < D_; d += 32) s += row[d] * conv_b[d];
#pragma unroll
            for (int o = 16; o; o >>= 1) s += __shfl_xor_sync(0xffffffffu, s, o);
            if (lane == 0) g_cb[e] = s;
        }
    }
}

// ---------------- kernel 2: fp16 HMMA GEMM, convert pipelined 1 chunk ahead --
#define KC      64
#define NCH     (D_ / KC)            // 8
#define ROWB    144
#define A_PLANE (128 * ROWB)         // 18432
#define A_SIZE  (3 * A_PLANE)        // 55296 per stage
#define RSF32   560                  // X fp32 row: 136 floats + pad
#define XF32_SZ (64 * RSF32)         // 35840 per stage
#define ROWXB   272                  // X fp16 row: 136 halfs
#define XF16_SZ (64 * ROWXB)         // 17408 per stage
#define XF32_OFF (2 * A_SIZE)                // 110592
#define XF16_OFF (XF32_OFF + 2 * XF32_SZ)    // 182272
#define GEMM_SMEM (XF16_OFF + 2 * XF16_SZ)   // 217088

__device__ __forceinline__ void load_A(uint32_t sb, int st, int ch,
                                       int e0, int t) {
    const int c0 = ch * KC;
    const uint32_t abase = sb + (uint32_t)st * A_SIZE;
#pragma unroll
    for (int p = 0; p < 6; p++) {
        int idx = p * 512 + t;
        int plane = idx >> 10;
        int rem = idx & 1023;
        int row = rem >> 3, cb = rem & 7;
        const __half* src = &g_A[plane][0][0] + (size_t)(e0 + row) * D_ + c0 + cb * 8;
        cp16(abase + plane * A_PLANE + row * ROWB + cb * 16, src);
    }
}
__device__ __forceinline__ void load_X(uint32_t sb, int st, int ch,
                                       int i0, int b, int t,
                                       const float* __restrict__ x) {
    const int c0 = ch * KC;
    const uint32_t xbase = sb + XF32_OFF + (uint32_t)st * XF32_SZ;
    for (int idx = t; idx < 64 * 34; idx += 512) {
        int row = idx / 34, cb = idx % 34;
        int ioff = i0 + cb * 4;
        int nb = (L_ - ioff) * 4;
        nb = nb < 0 ? 0 : (nb > 16 ? 16 : nb);
        const float* src = x + ((size_t)(b * D_ + c0 + row)) * L_ + (nb > 0 ? ioff : 0);
        cp16z(xbase + row * RSF32 + cb * 16, src, nb);
    }
}
__device__ __forceinline__ void convert_X(char* smem, int k, int t) {
    const char* xf = smem + XF32_OFF + (k & 1) * XF32_SZ;
    char* xh = smem + XF16_OFF + (k & 1) * XF16_SZ;
#pragma unroll
    for (int it = 0; it < 5; it++) {
        int idx = it * 512 + t;
        if (idx < 64 * 34) {
            int row = idx / 34, c4 = idx % 34;
            float4 v = *(const float4*)(xf + row * RSF32 + c4 * 16);
            __half2 h0 = __floats2half2_rn(v.x, v.y);
            __half2 h1 = __floats2half2_rn(v.z, v.w);
            uint2 u; u.x = *(uint32_t*)&h0; u.y = *(uint32_t*)&h1;
            *(uint2*)(xh + row * ROWXB + c4 * 8) = u;
        }
    }
}

__global__ void __launch_bounds__(512, 1) gemm_kernel(const float* __restrict__ x) {
    extern __shared__ char smem[];
    const uint32_t sb = smem_u32(smem);
    const int t = threadIdx.x, wid = t >> 5, lane = t & 31;
    const int i0 = blockIdx.x * 128, e0 = blockIdx.y * 128, b = blockIdx.z;
    const int e_w = (wid & 3) * 32;
    const int i_w = (wid >> 2) * 32;

    float accE[2][4][4], accO[2][4][4];
#pragma unroll
    for (int mt = 0; mt < 2; mt++)
#pragma unroll
        for (int nt = 0; nt < 4; nt++)
#pragma unroll
            for (int j = 0; j < 4; j++) { accE[mt][nt][j] = 0.f; accO[mt][nt][j] = 0.f; }

    // prologue: A0+X0 (group), X1 (group); convert chunk 0
    load_A(sb, 0, 0, e0, t);
    load_X(sb, 0, 0, i0, b, t, x);
    CP_COMMIT();
    load_X(sb, 1, 1, i0, b, t, x);
    CP_COMMIT();
    CP_WAIT1();
    __syncthreads();
    convert_X(smem, 0, t);

    const uint32_t xRowT  = (uint32_t)((lane & 7) + ((lane >> 3) & 1) * 8) * ROWXB
                          + (uint32_t)(i_w + (lane >> 4) * 8) * 2;
    const uint32_t xRowT2 = (uint32_t)((lane & 7) + ((lane >> 3) & 1) * 8) * ROWXB
                          + (uint32_t)(i_w + 32) * 2;
    const uint32_t aRow = (uint32_t)(e_w + (lane & 15)) * ROWB + (uint32_t)(lane >> 4) * 16;
    const int srcLaneHi = (lane + 4) & 31;
    const int srcLaneLo = lane & 3;
    const bool inBody = (lane < 28);

    for (int ch = 0; ch < NCH; ++ch) {
        CP_WAIT0();
        __syncthreads();   // A(ch) + X(ch+1) arrived; h(ch) converted prev iter

        if (ch + 1 < NCH) convert_X(smem, ch + 1, t);   // overlaps with MMA below
        if (ch + 1 < NCH) { load_A(sb, (ch + 1) & 1, ch + 1, e0, t); CP_COMMIT(); }
        if (ch + 2 < NCH) { load_X(sb, ch & 1, ch + 2, i0, b, t, x); CP_COMMIT(); }

        const uint32_t sA  = sb + (uint32_t)(ch & 1) * A_SIZE;
        const uint32_t sXh = sb + XF16_OFF + (uint32_t)(ch & 1) * XF16_SZ;

#pragma unroll
        for (int kh = 0; kh < 4; ++kh) {
            const uint32_t kbA = (uint32_t)kh * 32;
            const uint32_t kbX = (uint32_t)kh * 16 * ROWXB;
            uint32_t bX[5][2], bS[4][2];
            {
                uint32_t r[4];
                ldsm_x4_t(r, sXh + xRowT + kbX);
                bX[0][0] = r[0]; bX[0][1] = r[1]; bX[1][0] = r[2]; bX[1][1] = r[3];
                ldsm_x4_t(r, sXh + xRowT + kbX + 32);
                bX[2][0] = r[0]; bX[2][1] = r[1]; bX[3][0] = r[2]; bX[3][1] = r[3];
                ldsm_x2_t(bX[4], sXh + xRowT2 + kbX);
            }
#pragma unroll
            for (int nt = 0; nt < 4; nt++)
#pragma unroll
                for (int q = 0; q < 2; q++) {
                    uint32_t hi = __shfl_sync(0xffffffffu, bX[nt][q], srcLaneHi);
                    uint32_t lo = __shfl_sync(0xffffffffu, bX[nt + 1][q], srcLaneLo);
                    bS[nt][q] = inBody ? hi : lo;
                }
#pragma unroll
            for (int s = 0; s < 3; ++s) {
                uint32_t aF[2][4];
#pragma unroll
                for (int mt = 0; mt < 2; mt++)
                    ldsm_x4(aF[mt], sA + s * A_PLANE + aRow + mt * (16 * ROWB) + kbA);
#pragma unroll
                for (int mt = 0; mt < 2; mt++)
#pragma unroll
                    for (int nt = 0; nt < 4; nt++) {
                        float* d = (s == 1) ? accE[mt][nt] : accO[mt][nt];
                        mma_fp16(d, aF[mt], (s == 2) ? bS[nt] : bX[nt]);
                    }
            }
        }
    }

    // ---- epilogue: interleave even/odd, add folded conv bias, write fp16 z ----
#pragma unroll
    for (int mt = 0; mt < 2; mt++) {
        int r0 = e0 + e_w + mt * 16 + (lane >> 2);
        float cb0 = g_cb[r0], cb1 = g_cb[r0 + 8];
#pragma unroll
        for (int nt = 0; nt < 4; nt++) {
            int ie = i0 + i_w + nt * 8 + (lane & 3) * 2;
            __half2 p0 = __floats2half2_rn(accE[mt][nt][0] + cb0, accO[mt][nt][0] + cb0);
            __half2 p1 = __floats2half2_rn(accE[mt][nt][1] + cb0, accO[mt][nt][1] + cb0);
            __half2 p2 = __floats2half2_rn(accE[mt][nt][2] + cb1, accO[mt][nt][2] + cb1);
            __half2 p3 = __floats2half2_rn(accE[mt][nt][3] + cb1, accO[mt][nt][3] + cb1);
            uint2 u0, u1;
            u0.x = *(uint32_t*)&p0; u0.y = *(uint32_t*)&p1;
            u1.x = *(uint32_t*)&p2; u1.y = *(uint32_t*)&p3;
            *(uint2*)(g_z + ((size_t)(b * D_ + r0)) * T_ + 2 * ie)     = u0;
            *(uint2*)(g_z + ((size_t)(b * D_ + r0 + 8)) * T_ + 2 * ie) = u1;
        }
    }
}

// ---------------- kernel 3: depthwise 17-tap AA, direct-gmem, f32x2 ---------
__device__ __forceinline__ void unp8(uint4 v, float* w) {
    const __half2* h = (const __half2*)&v;
    float2 f0 = __half22float2(h[0]);
    float2 f1 = __half22float2(h[1]);
    float2 f2 = __half22float2(h[2]);
    float2 f3 = __half22float2(h[3]);
    w[0] = f0.x; w[1] = f0.y; w[2] = f1.x; w[3] = f1.y;
    w[4] = f2.x; w[5] = f2.y; w[6] = f3.x; w[7] = f3.y;
}

__global__ __launch_bounds__(256) void aa_kernel(const float* __restrict__ aa,
                                                 const float* __restrict__ pb,
                                                 float* __restrict__ out) {
    const int row = blockIdx.x >> 2;
    const int seg = blockIdx.x & 3;
    const int t   = threadIdx.x;
    const int o0  = seg * 2048 + t * 8;
    const __half* zr = g_z + (size_t)row * T_;

    float w[24];
    if (o0 >= 8 && o0 + 16 <= T_) {
        uint4 v0 = *(const uint4*)(zr + o0 - 8);
        uint4 v1 = *(const uint4*)(zr + o0);
        uint4 v2 = *(const uint4*)(zr + o0 + 8);
        unp8(v0, w); unp8(v1, w + 8); unp8(v2, w + 16);
    } else {
#pragma unroll
        for (int j = 0; j < 24; j++) {
            int g = o0 - 8 + j;
            w[j] = (g >= 0 && g < T_) ? __half2float(zr[g]) : 0.f;
        }
    }

    float kc[KS];
#pragma unroll
    for (int j = 0; j < KS; j++) kc[j] = __ldg(&aa[j]);
    float bias = __ldg(&pb[row & (D_ - 1)]);

    unsigned long long E[12], O[11], acc[4];
#pragma unroll
    for (int m = 0; m < 12; m++) E[m] = pack2(w[2 * m], w[2 * m + 1]);
#pragma unroll
    for (int m = 0; m < 11; m++) O[m] = pack2(w[2 * m + 1], w[2 * m + 2]);
    unsigned long long b2 = pack2(bias, bias);
#pragma unroll
    for (int p = 0; p < 4; p++) acc[p] = b2;

#pragma unroll
    for (int j = 0; j < KS; j++) {
        unsigned long long k2 = pack2(kc[j], kc[j]);
        const unsigned long long* src = (j & 1) ? &O[j >> 1] : &E[j >> 1];
#pragma unroll
        for (int p = 0; p < 4; p++) acc[p] = fma2(k2, src[p], acc[p]);
    }

    float* op = out + (size_t)row * T_ + o0;
    float2 a0 = unpack2(acc[0]), a1 = unpack2(acc[1]);
    float2 a2 = unpack2(acc[2]), a3 = unpack2(acc[3]);
    float4 v0, v1;
    v0.x = a0.x; v0.y = a0.y; v0.z = a1.x; v0.w = a1.y;
    v1.x = a2.x; v1.y = a2.y; v1.z = a3.x; v1.w = a3.y;
    *(float4*)op       = v0;
    *(float4*)(op + 4) = v1;
}

// ---------------- launch ----------------
extern "C" void kernel_launch(void* const* d_in, const int* in_sizes, int n_in,
                              void* d_out, int out_size) {
    const float* x      = (const float*)d_in[0];
    const float* conv_w = (const float*)d_in[1];
    const float* conv_b = (const float*)d_in[2];
    const float* aa_k   = (const float*)d_in[3];
    const float* proj_w = (const float*)d_in[4];
    const float* proj_b = (const float*)d_in[5];
    float* out = (float*)d_out;

    cudaFuncSetAttribute(gemm_kernel, cudaFuncAttributeMaxDynamicSharedMemorySize, GEMM_SMEM);
    cudaFuncSetAttribute(prep_kernel, cudaFuncAttributeMaxDynamicSharedMemorySize, PREP_SMEM);

    prep_kernel<<<dim3(PREP_GRID), 256, PREP_SMEM>>>(conv_w, conv_b, proj_w);
    gemm_kernel<<<dim3(L_ / 128, D_ / 128, B_), 512, GEMM_SMEM>>>(x);
    aa_kernel<<<dim3(B_ * D_ * 4), 256>>>(aa_k, proj_b, out);
}

// round 15
// speedup vs baseline: 1.1274x; 1.1274x over previous
#include <cuda_runtime.h>
#include <cuda_fp16.h>
#include <cstdint>

#define B_   8
#define D_   512
#define L_   4096
#define T_   8192
#define KS   17

// ---------------- device scratch ----------------
__device__ __half g_A[3][D_][D_];         // folded weights fp16 [k][e][c]
__device__ float  g_cb[D_];               // projected conv bias
__device__ __half g_z[(size_t)B_ * D_ * T_];   // intermediate (67 MB, fp16)

// ---------------- PTX helpers ----------------
__device__ __forceinline__ uint32_t smem_u32(const void* p) {
    uint32_t a;
    asm("{ .reg .u64 t; cvta.to.shared.u64 t, %1; cvt.u32.u64 %0, t; }" : "=r"(a) : "l"(p));
    return a;
}
__device__ __forceinline__ void cp16(uint32_t dst, const void* src) {
    asm volatile("cp.async.cg.shared.global [%0], [%1], 16;" :: "r"(dst), "l"(src));
}
__device__ __forceinline__ void cp16z(uint32_t dst, const void* src, int nbytes) {
    asm volatile("cp.async.cg.shared.global [%0], [%1], 16, %2;"
                 :: "r"(dst), "l"(src), "r"(nbytes));
}
#define CP_COMMIT()  asm volatile("cp.async.commit_group;" ::: "memory")
#define CP_WAIT0()   asm volatile("cp.async.wait_group 0;" ::: "memory")
#define CP_WAIT1()   asm volatile("cp.async.wait_group 1;" ::: "memory")

__device__ __forceinline__ void ldsm_x4(uint32_t* r, uint32_t addr) {
    asm volatile("ldmatrix.sync.aligned.m8n8.x4.shared.b16 {%0,%1,%2,%3}, [%4];"
                 : "=r"(r[0]), "=r"(r[1]), "=r"(r[2]), "=r"(r[3]) : "r"(addr));
}
__device__ __forceinline__ void ldsm_x4_t(uint32_t* r, uint32_t addr) {
    asm volatile("ldmatrix.sync.aligned.m8n8.x4.trans.shared.b16 {%0,%1,%2,%3}, [%4];"
                 : "=r"(r[0]), "=r"(r[1]), "=r"(r[2]), "=r"(r[3]) : "r"(addr));
}
__device__ __forceinline__ void ldsm_x2_t(uint32_t* r, uint32_t addr) {
    asm volatile("ldmatrix.sync.aligned.m8n8.x2.trans.shared.b16 {%0,%1}, [%2];"
                 : "=r"(r[0]), "=r"(r[1]) : "r"(addr));
}
__device__ __forceinline__ void mma_fp16(float* d, const uint32_t* a, const uint32_t* b) {
    asm volatile("mma.sync.aligned.m16n8k16.row.col.f32.f16.f16.f32 "
                 "{%0,%1,%2,%3}, {%4,%5,%6,%7}, {%8,%9}, {%0,%1,%2,%3};"
                 : "+f"(d[0]), "+f"(d[1]), "+f"(d[2]), "+f"(d[3])
                 : "r"(a[0]), "r"(a[1]), "r"(a[2]), "r"(a[3]), "r"(b[0]), "r"(b[1]));
}
__device__ __forceinline__ unsigned long long pack2(float lo, float hi) {
    unsigned long long r;
    asm("mov.b64 %0, {%1, %2};" : "=l"(r) : "f"(lo), "f"(hi));
    return r;
}
__device__ __forceinline__ unsigned long long fma2(unsigned long long a,
                                                   unsigned long long b,
                                                   unsigned long long c) {
    unsigned long long d;
    asm("fma.rn.f32x2 %0, %1, %2, %3;" : "=l"(d) : "l"(a), "l"(b), "l"(c));
    return d;
}
__device__ __forceinline__ float2 unpack2(unsigned long long v) {
    float2 f;
    asm("mov.b64 {%0, %1}, %2;" : "=f"(f.x), "=f"(f.y) : "l"(v));
    return f;
}

// ---------------- kernel 1: prep = HMMA fold | cb (round-13 version) --------
// blocks [0,96)  : fold GEMM  fold[e][n] = sum_d P[e][d] W[d][n], n = c*3+k
//                  tile 128e x 64n, K-chunk 64 d, scatter-write to g_A[k][e][c]
// blocks [96,98) : cb (warp-cooperative)
#define FOLD_BLKS 96
#define PREP_GRID (FOLD_BLKS + 2)
#define FROWB 144                       // smem row: 64 halfs + 8 pad = 144 B
#define FA_BYTES (128 * FROWB)          // 18432
#define FB_BYTES (64 * FROWB)           // 9216

__global__ __launch_bounds__(256) void prep_kernel(const float* __restrict__ conv_w,
                                                   const float* __restrict__ conv_b,
                                                   const float* __restrict__ proj_w) {
    __shared__ char psm[FA_BYTES + FB_BYTES];
    const int bx = blockIdx.x;
    const int t  = threadIdx.x;

    if (bx < FOLD_BLKS) {
        const int e0 = (bx / 24) * 128;
        const int n0 = (bx % 24) * 64;
        const uint32_t sA = smem_u32(psm);
        const uint32_t sB = sA + FA_BYTES;
        __half* hA = (__half*)psm;
        __half* hB = (__half*)(psm + FA_BYTES);
        const int wid = t >> 5, lane = t & 31;
        const int e_w = (wid & 3) * 32;
        const int n_w = (wid >> 2) * 32;

        float acc[2][4][4];
#pragma unroll
        for (int mt = 0; mt < 2; mt++)
#pragma unroll
            for (int nt = 0; nt < 4; nt++)
#pragma unroll
                for (int j = 0; j < 4; j++) acc[mt][nt][j] = 0.f;

        const uint32_t aRow = (uint32_t)(e_w + (lane & 15)) * FROWB + (uint32_t)(lane >> 4) * 16;
        const uint32_t bOff = (uint32_t)((lane & 7) + ((lane >> 3) & 1) * 8) * FROWB
                            + (uint32_t)(n_w + (lane >> 4) * 8) * 2;

        for (int d0 = 0; d0 < D_; d0 += 64) {
            // P chunk: 128 e-rows x 64 d  (fp32 -> fp16), 8 float4/thread
#pragma unroll
            for (int p = 0; p < 8; p++) {
                int idx = p * 256 + t;
                int row = idx >> 4, q = idx & 15;
                float4 v = *(const float4*)(proj_w + (size_t)(e0 + row) * D_ + d0 + q * 4);
                __half2 h0 = __floats2half2_rn(v.x, v.y);
                __half2 h1 = __floats2half2_rn(v.z, v.w);
                uint2 u; u.x = *(uint32_t*)&h0; u.y = *(uint32_t*)&h1;
                *(uint2*)&hA[row * 72 + q * 4] = u;
            }
            // W chunk: 64 d-rows x 64 n, 4 float4/thread
#pragma unroll
            for (int p = 0; p < 4; p++) {
                int idx = p * 256 + t;
                int row = idx >> 4, q = idx & 15;
                float4 v = *(const float4*)(conv_w + (size_t)(d0 + row) * (3 * D_) + n0 + q * 4);
                __half2 h0 = __floats2half2_rn(v.x, v.y);
                __half2 h1 = __floats2half2_rn(v.z, v.w);
                uint2 u; u.x = *(uint32_t*)&h0; u.y = *(uint32_t*)&h1;
                *(uint2*)&hB[row * 72 + q * 4] = u;
            }
            __syncthreads();
#pragma unroll
            for (int kh = 0; kh < 4; ++kh) {
                uint32_t aF[2][4], bF[4][2];
#pragma unroll
                for (int mt = 0; mt < 2; mt++)
                    ldsm_x4(aF[mt], sA + aRow + mt * (16 * FROWB) + kh * 32);
                {
                    uint32_t r[4];
                    uint32_t base = sB + bOff + (uint32_t)kh * 16 * FROWB;
                    ldsm_x4_t(r, base);
                    bF[0][0] = r[0]; bF[0][1] = r[1]; bF[1][0] = r[2]; bF[1][1] = r[3];
                    ldsm_x4_t(r, base + 32);
                    bF[2][0] = r[0]; bF[2][1] = r[1]; bF[3][0] = r[2]; bF[3][1] = r[3];
                }
#pragma unroll
                for (int mt = 0; mt < 2; mt++)
#pragma unroll
                    for (int nt = 0; nt < 4; nt++)
                        mma_fp16(acc[mt][nt], aF[mt], bF[nt]);
            }
            __syncthreads();
        }
        // scatter epilogue: D[e][n] -> g_A[n%3][e][n/3]
#pragma unroll
        for (int mt = 0; mt < 2; mt++) {
            int eb = e0 + e_w + mt * 16 + (lane >> 2);
#pragma unroll
            for (int nt = 0; nt < 4; nt++) {
                int nb = n0 + n_w + nt * 8 + (lane & 3) * 2;
#pragma unroll
                for (int j = 0; j < 4; j++) {
                    int e = eb + ((j >> 1) ? 8 : 0);
                    int n = nb + (j & 1);
                    g_A[n % 3][e][n / 3] = __float2half_rn(acc[mt][nt][j]);
                }
            }
        }
    } else {
        // ---- cb: warp per 32 e, coalesced reads + shfl reduce ----
        const int warp = t >> 5, lane = t & 31;
        const int ebase = (bx - FOLD_BLKS) * 256 + warp * 32;
#pragma unroll 4
        for (int eo = 0; eo < 32; eo++) {
            int e = ebase + eo;
            const float* row = proj_w + (size_t)e * D_;
            float s = 0.f;
#pragma unroll
            for (int d = lane; d < D_; d += 32) s += row[d] * conv_b[d];
#pragma unroll
            for (int o = 16; o; o >>= 1) s += __shfl_xor_sync(0xffffffffu, s, o);
            if (lane == 0) g_cb[e] = s;
        }
    }
}

// ---------------- kernel 2: fp16 HMMA GEMM, convert pipelined 1 chunk ahead --
#define KC      64
#define NCH     (D_ / KC)            // 8
#define ROWB    144
#define A_PLANE (128 * ROWB)         // 18432
#define A_SIZE  (3 * A_PLANE)        // 55296 per stage
#define RSF32   560                  // X fp32 row: 136 floats + pad
#define XF32_SZ (64 * RSF32)         // 35840 per stage
#define ROWXB   272                  // X fp16 row: 136 halfs
#define XF16_SZ (64 * ROWXB)         // 17408 per stage
#define XF32_OFF (2 * A_SIZE)                // 110592
#define XF16_OFF (XF32_OFF + 2 * XF32_SZ)    // 182272
#define GEMM_SMEM (XF16_OFF + 2 * XF16_SZ)   // 217088

__device__ __forceinline__ void load_A(uint32_t sb, int st, int ch,
                                       int e0, int t) {
    const int c0 = ch * KC;
    const uint32_t abase = sb + (uint32_t)st * A_SIZE;
#pragma unroll
    for (int p = 0; p < 6; p++) {
        int idx = p * 512 + t;
        int plane = idx >> 10;
        int rem = idx & 1023;
        int row = rem >> 3, cb = rem & 7;
        const __half* src = &g_A[plane][0][0] + (size_t)(e0 + row) * D_ + c0 + cb * 8;
        cp16(abase + plane * A_PLANE + row * ROWB + cb * 16, src);
    }
}
__device__ __forceinline__ void load_X(uint32_t sb, int st, int ch,
                                       int i0, int b, int t,
                                       const float* __restrict__ x) {
    const int c0 = ch * KC;
    const uint32_t xbase = sb + XF32_OFF + (uint32_t)st * XF32_SZ;
    for (int idx = t; idx < 64 * 34; idx += 512) {
        int row = idx / 34, cb = idx % 34;
        int ioff = i0 + cb * 4;
        int nb = (L_ - ioff) * 4;
        nb = nb < 0 ? 0 : (nb > 16 ? 16 : nb);
        const float* src = x + ((size_t)(b * D_ + c0 + row)) * L_ + (nb > 0 ? ioff : 0);
        cp16z(xbase + row * RSF32 + cb * 16, src, nb);
    }
}
__device__ __forceinline__ void convert_X(char* smem, int k, int t) {
    const char* xf = smem + XF32_OFF + (k & 1) * XF32_SZ;
    char* xh = smem + XF16_OFF + (k & 1) * XF16_SZ;
#pragma unroll
    for (int it = 0; it < 5; it++) {
        int idx = it * 512 + t;
        if (idx < 64 * 34) {
            int row = idx / 34, c4 = idx % 34;
            float4 v = *(const float4*)(xf + row * RSF32 + c4 * 16);
            __half2 h0 = __floats2half2_rn(v.x, v.y);
            __half2 h1 = __floats2half2_rn(v.z, v.w);
            uint2 u; u.x = *(uint32_t*)&h0; u.y = *(uint32_t*)&h1;
            *(uint2*)(xh + row * ROWXB + c4 * 8) = u;
        }
    }
}

__global__ void __launch_bounds__(512, 1) gemm_kernel(const float* __restrict__ x) {
    extern __shared__ char smem[];
    const uint32_t sb = smem_u32(smem);
    const int t = threadIdx.x, wid = t >> 5, lane = t & 31;
    const int i0 = blockIdx.x * 128, e0 = blockIdx.y * 128, b = blockIdx.z;
    const int e_w = (wid & 3) * 32;
    const int i_w = (wid >> 2) * 32;

    float accE[2][4][4], accO[2][4][4];
#pragma unroll
    for (int mt = 0; mt < 2; mt++)
#pragma unroll
        for (int nt = 0; nt < 4; nt++)
#pragma unroll
            for (int j = 0; j < 4; j++) { accE[mt][nt][j] = 0.f; accO[mt][nt][j] = 0.f; }

    // prologue: A0+X0 (group), X1 (group); convert chunk 0
    load_A(sb, 0, 0, e0, t);
    load_X(sb, 0, 0, i0, b, t, x);
    CP_COMMIT();
    load_X(sb, 1, 1, i0, b, t, x);
    CP_COMMIT();
    CP_WAIT1();
    __syncthreads();
    convert_X(smem, 0, t);

    const uint32_t xRowT  = (uint32_t)((lane & 7) + ((lane >> 3) & 1) * 8) * ROWXB
                          + (uint32_t)(i_w + (lane >> 4) * 8) * 2;
    const uint32_t xRowT2 = (uint32_t)((lane & 7) + ((lane >> 3) & 1) * 8) * ROWXB
                          + (uint32_t)(i_w + 32) * 2;
    const uint32_t aRow = (uint32_t)(e_w + (lane & 15)) * ROWB + (uint32_t)(lane >> 4) * 16;
    const int srcLaneHi = (lane + 4) & 31;
    const int srcLaneLo = lane & 3;
    const bool inBody = (lane < 28);

    for (int ch = 0; ch < NCH; ++ch) {
        CP_WAIT0();
        __syncthreads();   // A(ch) + X(ch+1) arrived; h(ch) converted prev iter

        if (ch + 1 < NCH) convert_X(smem, ch + 1, t);   // overlaps with MMA below
        if (ch + 1 < NCH) { load_A(sb, (ch + 1) & 1, ch + 1, e0, t); CP_COMMIT(); }
        if (ch + 2 < NCH) { load_X(sb, ch & 1, ch + 2, i0, b, t, x); CP_COMMIT(); }

        const uint32_t sA  = sb + (uint32_t)(ch & 1) * A_SIZE;
        const uint32_t sXh = sb + XF16_OFF + (uint32_t)(ch & 1) * XF16_SZ;

#pragma unroll
        for (int kh = 0; kh < 4; ++kh) {
            const uint32_t kbA = (uint32_t)kh * 32;
            const uint32_t kbX = (uint32_t)kh * 16 * ROWXB;
            uint32_t bX[5][2], bS[4][2];
            {
                uint32_t r[4];
                ldsm_x4_t(r, sXh + xRowT + kbX);
                bX[0][0] = r[0]; bX[0][1] = r[1]; bX[1][0] = r[2]; bX[1][1] = r[3];
                ldsm_x4_t(r, sXh + xRowT + kbX + 32);
                bX[2][0] = r[0]; bX[2][1] = r[1]; bX[3][0] = r[2]; bX[3][1] = r[3];
                ldsm_x2_t(bX[4], sXh + xRowT2 + kbX);
            }
#pragma unroll
            for (int nt = 0; nt < 4; nt++)
#pragma unroll
                for (int q = 0; q < 2; q++) {
                    uint32_t hi = __shfl_sync(0xffffffffu, bX[nt][q], srcLaneHi);
                    uint32_t lo = __shfl_sync(0xffffffffu, bX[nt + 1][q], srcLaneLo);
                    bS[nt][q] = inBody ? hi : lo;
                }
#pragma unroll
            for (int s = 0; s < 3; ++s) {
                uint32_t aF[2][4];
#pragma unroll
                for (int mt = 0; mt < 2; mt++)
                    ldsm_x4(aF[mt], sA + s * A_PLANE + aRow + mt * (16 * ROWB) + kbA);
#pragma unroll
                for (int mt = 0; mt < 2; mt++)
#pragma unroll
                    for (int nt = 0; nt < 4; nt++) {
                        float* d = (s == 1) ? accE[mt][nt] : accO[mt][nt];
                        mma_fp16(d, aF[mt], (s == 2) ? bS[nt] : bX[nt]);
                    }
            }
        }
    }

    // ---- epilogue: interleave even/odd, add folded conv bias, write fp16 z ----
#pragma unroll
    for (int mt = 0; mt < 2; mt++) {
        int r0 = e0 + e_w + mt * 16 + (lane >> 2);
        float cb0 = g_cb[r0], cb1 = g_cb[r0 + 8];
#pragma unroll
        for (int nt = 0; nt < 4; nt++) {
            int ie = i0 + i_w + nt * 8 + (lane & 3) * 2;
            __half2 p0 = __floats2half2_rn(accE[mt][nt][0] + cb0, accO[mt][nt][0] + cb0);
            __half2 p1 = __floats2half2_rn(accE[mt][nt][1] + cb0, accO[mt][nt][1] + cb0);
            __half2 p2 = __floats2half2_rn(accE[mt][nt][2] + cb1, accO[mt][nt][2] + cb1);
            __half2 p3 = __floats2half2_rn(accE[mt][nt][3] + cb1, accO[mt][nt][3] + cb1);
            uint2 u0, u1;
            u0.x = *(uint32_t*)&p0; u0.y = *(uint32_t*)&p1;
            u1.x = *(uint32_t*)&p2; u1.y = *(uint32_t*)&p3;
            *(uint2*)(g_z + ((size_t)(b * D_ + r0)) * T_ + 2 * ie)     = u0;
            *(uint2*)(g_z + ((size_t)(b * D_ + r0 + 8)) * T_ + 2 * ie) = u1;
        }
    }
}

// ---------------- kernel 3: depthwise 17-tap AA, direct-gmem, f32x2 ---------
__device__ __forceinline__ void unp8(uint4 v, float* w) {
    const __half2* h = (const __half2*)&v;
    float2 f0 = __half22float2(h[0]);
    float2 f1 = __half22float2(h[1]);
    float2 f2 = __half22float2(h[2]);
    float2 f3 = __half22float2(h[3]);
    w[0] = f0.x; w[1] = f0.y; w[2] = f1.x; w[3] = f1.y;
    w[4] = f2.x; w[5] = f2.y; w[6] = f3.x; w[7] = f3.y;
}

__global__ __launch_bounds__(256) void aa_kernel(const float* __restrict__ aa,
                                                 const float* __restrict__ pb,
                                                 float* __restrict__ out) {
    const int row = blockIdx.x >> 2;
    const int seg = blockIdx.x & 3;
    const int t   = threadIdx.x;
    const int o0  = seg * 2048 + t * 8;
    const __half* zr = g_z + (size_t)row * T_;

    float w[24];
    if (o0 >= 8 && o0 + 16 <= T_) {
        uint4 v0 = *(const uint4*)(zr + o0 - 8);
        uint4 v1 = *(const uint4*)(zr + o0);
        uint4 v2 = *(const uint4*)(zr + o0 + 8);
        unp8(v0, w); unp8(v1, w + 8); unp8(v2, w + 16);
    } else {
#pragma unroll
        for (int j = 0; j < 24; j++) {
            int g = o0 - 8 + j;
            w[j] = (g >= 0 && g < T_) ? __half2float(zr[g]) : 0.f;
        }
    }

    float kc[KS];
#pragma unroll
    for (int j = 0; j < KS; j++) kc[j] = __ldg(&aa[j]);
    float bias = __ldg(&pb[row & (D_ - 1)]);

    unsigned long long E[12], O[11], acc[4];
#pragma unroll
    for (int m = 0; m < 12; m++) E[m] = pack2(w[2 * m], w[2 * m + 1]);
#pragma unroll
    for (int m = 0; m < 11; m++) O[m] = pack2(w[2 * m + 1], w[2 * m + 2]);
    unsigned long long b2 = pack2(bias, bias);
#pragma unroll
    for (int p = 0; p < 4; p++) acc[p] = b2;

#pragma unroll
    for (int j = 0; j < KS; j++) {
        unsigned long long k2 = pack2(kc[j], kc[j]);
        const unsigned long long* src = (j & 1) ? &O[j >> 1] : &E[j >> 1];
#pragma unroll
        for (int p = 0; p < 4; p++) acc[p] = fma2(k2, src[p], acc[p]);
    }

    float* op = out + (size_t)row * T_ + o0;
    float2 a0 = unpack2(acc[0]), a1 = unpack2(acc[1]);
    float2 a2 = unpack2(acc[2]), a3 = unpack2(acc[3]);
    float4 v0, v1;
    v0.x = a0.x; v0.y = a0.y; v0.z = a1.x; v0.w = a1.y;
    v1.x = a2.x; v1.y = a2.y; v1.z = a3.x; v1.w = a3.y;
    *(float4*)op       = v0;
    *(float4*)(op + 4) = v1;
}

// ---------------- launch ----------------
extern "C" void kernel_launch(void* const* d_in, const int* in_sizes, int n_in,
                              void* d_out, int out_size) {
    const float* x      = (const float*)d_in[0];
    const float* conv_w = (const float*)d_in[1];
    const float* conv_b = (const float*)d_in[2];
    const float* aa_k   = (const float*)d_in[3];
    const float* proj_w = (const float*)d_in[4];
    const float* proj_b = (const float*)d_in[5];
    float* out = (float*)d_out;

    cudaFuncSetAttribute(gemm_kernel, cudaFuncAttributeMaxDynamicSharedMemorySize, GEMM_SMEM);

    prep_kernel<<<dim3(PREP_GRID), 256>>>(conv_w, conv_b, proj_w);
    gemm_kernel<<<dim3(L_ / 128, D_ / 128, B_), 512, GEMM_SMEM>>>(x);
    aa_kernel<<<dim3(B_ * D_ * 4), 256>>>(aa_k, proj_b, out);
}

// round 16
// speedup vs baseline: 1.1381x; 1.0095x over previous
#include <cuda_runtime.h>
#include <cuda_fp16.h>
#include <cstdint>

#define B_   8
#define D_   512
#define L_   4096
#define T_   8192
#define KS   17

// ---------------- device scratch ----------------
__device__ __half g_A[3][D_][D_];         // folded weights fp16 [k][e][c]
__device__ float  g_cb[D_];               // projected conv bias
__device__ __half g_z[(size_t)B_ * D_ * T_];   // intermediate (67 MB, fp16)

// ---------------- PTX helpers ----------------
__device__ __forceinline__ uint32_t smem_u32(const void* p) {
    uint32_t a;
    asm("{ .reg .u64 t; cvta.to.shared.u64 t, %1; cvt.u32.u64 %0, t; }" : "=r"(a) : "l"(p));
    return a;
}
__device__ __forceinline__ void cp16(uint32_t dst, const void* src) {
    asm volatile("cp.async.cg.shared.global [%0], [%1], 16;" :: "r"(dst), "l"(src));
}
__device__ __forceinline__ void cp16z(uint32_t dst, const void* src, int nbytes) {
    asm volatile("cp.async.cg.shared.global [%0], [%1], 16, %2;"
                 :: "r"(dst), "l"(src), "r"(nbytes));
}
#define CP_COMMIT()  asm volatile("cp.async.commit_group;" ::: "memory")
#define CP_WAIT0()   asm volatile("cp.async.wait_group 0;" ::: "memory")
#define CP_WAIT1()   asm volatile("cp.async.wait_group 1;" ::: "memory")

__device__ __forceinline__ void ldsm_x4(uint32_t* r, uint32_t addr) {
    asm volatile("ldmatrix.sync.aligned.m8n8.x4.shared.b16 {%0,%1,%2,%3}, [%4];"
                 : "=r"(r[0]), "=r"(r[1]), "=r"(r[2]), "=r"(r[3]) : "r"(addr));
}
__device__ __forceinline__ void ldsm_x4_t(uint32_t* r, uint32_t addr) {
    asm volatile("ldmatrix.sync.aligned.m8n8.x4.trans.shared.b16 {%0,%1,%2,%3}, [%4];"
                 : "=r"(r[0]), "=r"(r[1]), "=r"(r[2]), "=r"(r[3]) : "r"(addr));
}
__device__ __forceinline__ void ldsm_x2_t(uint32_t* r, uint32_t addr) {
    asm volatile("ldmatrix.sync.aligned.m8n8.x2.trans.shared.b16 {%0,%1}, [%2];"
                 : "=r"(r[0]), "=r"(r[1]) : "r"(addr));
}
__device__ __forceinline__ void mma_fp16(float* d, const uint32_t* a, const uint32_t* b) {
    asm volatile("mma.sync.aligned.m16n8k16.row.col.f32.f16.f16.f32 "
                 "{%0,%1,%2,%3}, {%4,%5,%6,%7}, {%8,%9}, {%0,%1,%2,%3};"
                 : "+f"(d[0]), "+f"(d[1]), "+f"(d[2]), "+f"(d[3])
                 : "r"(a[0]), "r"(a[1]), "r"(a[2]), "r"(a[3]), "r"(b[0]), "r"(b[1]));
}
__device__ __forceinline__ unsigned long long pack2(float lo, float hi) {
    unsigned long long r;
    asm("mov.b64 %0, {%1, %2};" : "=l"(r) : "f"(lo), "f"(hi));
    return r;
}
__device__ __forceinline__ unsigned long long fma2(unsigned long long a,
                                                   unsigned long long b,
                                                   unsigned long long c) {
    unsigned long long d;
    asm("fma.rn.f32x2 %0, %1, %2, %3;" : "=l"(d) : "l"(a), "l"(b), "l"(c));
    return d;
}
__device__ __forceinline__ float2 unpack2(unsigned long long v) {
    float2 f;
    asm("mov.b64 {%0, %1}, %2;" : "=f"(f.x), "=f"(f.y) : "l"(v));
    return f;
}

// ---------------- kernel 1: prep = HMMA fold (64e x 64n, 192 blks) | cb -----
// fold[e][n] = sum_d P[e][d] W[d][n], n = c*3+k; scatter to g_A[k][e][c]
#define FOLD_BLKS 192
#define PREP_GRID (FOLD_BLKS + 2)
#define FROWB 144                       // smem row: 64 halfs + 8 pad = 144 B
#define FA_BYTES (64 * FROWB)           // 9216
#define FB_BYTES (64 * FROWB)           // 9216

__global__ __launch_bounds__(256) void prep_kernel(const float* __restrict__ conv_w,
                                                   const float* __restrict__ conv_b,
                                                   const float* __restrict__ proj_w) {
    __shared__ char psm[FA_BYTES + FB_BYTES];
    const int bx = blockIdx.x;
    const int t  = threadIdx.x;

    if (bx < FOLD_BLKS) {
        const int e0 = (bx / 24) * 64;
        const int n0 = (bx % 24) * 64;
        const uint32_t sA = smem_u32(psm);
        const uint32_t sB = sA + FA_BYTES;
        __half* hA = (__half*)psm;
        __half* hB = (__half*)(psm + FA_BYTES);
        const int wid = t >> 5, lane = t & 31;
        const int e_w = (wid & 1) * 32;       // 2 e-groups of 32
        const int n_w = (wid >> 1) * 16;      // 4 n-groups of 16

        float acc[2][2][4];
#pragma unroll
        for (int mt = 0; mt < 2; mt++)
#pragma unroll
            for (int nt = 0; nt < 2; nt++)
#pragma unroll
                for (int j = 0; j < 4; j++) acc[mt][nt][j] = 0.f;

        const uint32_t aRow = (uint32_t)(e_w + (lane & 15)) * FROWB + (uint32_t)(lane >> 4) * 16;
        const uint32_t bOff = (uint32_t)((lane & 7) + ((lane >> 3) & 1) * 8) * FROWB
                            + (uint32_t)(n_w + (lane >> 4) * 8) * 2;

        for (int d0 = 0; d0 < D_; d0 += 64) {
            // P chunk: 64 e-rows x 64 d (fp32 -> fp16), 4 float4/thread
#pragma unroll
            for (int p = 0; p < 4; p++) {
                int idx = p * 256 + t;
                int row = idx >> 4, q = idx & 15;
                float4 v = *(const float4*)(proj_w + (size_t)(e0 + row) * D_ + d0 + q * 4);
                __half2 h0 = __floats2half2_rn(v.x, v.y);
                __half2 h1 = __floats2half2_rn(v.z, v.w);
                uint2 u; u.x = *(uint32_t*)&h0; u.y = *(uint32_t*)&h1;
                *(uint2*)&hA[row * 72 + q * 4] = u;
            }
            // W chunk: 64 d-rows x 64 n, 4 float4/thread
#pragma unroll
            for (int p = 0; p < 4; p++) {
                int idx = p * 256 + t;
                int row = idx >> 4, q = idx & 15;
                float4 v = *(const float4*)(conv_w + (size_t)(d0 + row) * (3 * D_) + n0 + q * 4);
                __half2 h0 = __floats2half2_rn(v.x, v.y);
                __half2 h1 = __floats2half2_rn(v.z, v.w);
                uint2 u; u.x = *(uint32_t*)&h0; u.y = *(uint32_t*)&h1;
                *(uint2*)&hB[row * 72 + q * 4] = u;
            }
            __syncthreads();
#pragma unroll
            for (int kh = 0; kh < 4; ++kh) {
                uint32_t aF[2][4], bF[2][2];
#pragma unroll
                for (int mt = 0; mt < 2; mt++)
                    ldsm_x4(aF[mt], sA + aRow + mt * (16 * FROWB) + kh * 32);
                {
                    uint32_t r[4];
                    ldsm_x4_t(r, sB + bOff + (uint32_t)kh * 16 * FROWB);
                    bF[0][0] = r[0]; bF[0][1] = r[1]; bF[1][0] = r[2]; bF[1][1] = r[3];
                }
#pragma unroll
                for (int mt = 0; mt < 2; mt++)
#pragma unroll
                    for (int nt = 0; nt < 2; nt++)
                        mma_fp16(acc[mt][nt], aF[mt], bF[nt]);
            }
            __syncthreads();
        }
        // scatter epilogue: D[e][n] -> g_A[n%3][e][n/3]
#pragma unroll
        for (int mt = 0; mt < 2; mt++) {
            int eb = e0 + e_w + mt * 16 + (lane >> 2);
#pragma unroll
            for (int nt = 0; nt < 2; nt++) {
                int nb = n0 + n_w + nt * 8 + (lane & 3) * 2;
#pragma unroll
                for (int j = 0; j < 4; j++) {
                    int e = eb + ((j >> 1) ? 8 : 0);
                    int n = nb + (j & 1);
                    g_A[n % 3][e][n / 3] = __float2half_rn(acc[mt][nt][j]);
                }
            }
        }
    } else {
        // ---- cb: warp per 32 e, coalesced reads + shfl reduce ----
        const int warp = t >> 5, lane = t & 31;
        const int ebase = (bx - FOLD_BLKS) * 256 + warp * 32;
#pragma unroll 4
        for (int eo = 0; eo < 32; eo++) {
            int e = ebase + eo;
            const float* row = proj_w + (size_t)e * D_;
            float s = 0.f;
#pragma unroll
            for (int d = lane; d < D_; d += 32) s += row[d] * conv_b[d];
#pragma unroll
            for (int o = 16; o; o >>= 1) s += __shfl_xor_sync(0xffffffffu, s, o);
            if (lane == 0) g_cb[e] = s;
        }
    }
}

// ---------------- kernel 2: fp16 HMMA GEMM, convert pipelined 1 chunk ahead --
#define KC      64
#define NCH     (D_ / KC)            // 8
#define ROWB    144
#define A_PLANE (128 * ROWB)         // 18432
#define A_SIZE  (3 * A_PLANE)        // 55296 per stage
#define RSF32   560                  // X fp32 row: 136 floats + pad
#define XF32_SZ (64 * RSF32)         // 35840 per stage
#define ROWXB   272                  // X fp16 row: 136 halfs
#define XF16_SZ (64 * ROWXB)         // 17408 per stage
#define XF32_OFF (2 * A_SIZE)                // 110592
#define XF16_OFF (XF32_OFF + 2 * XF32_SZ)    // 182272
#define GEMM_SMEM (XF16_OFF + 2 * XF16_SZ)   // 217088

__device__ __forceinline__ void load_A(uint32_t sb, int st, int ch,
                                       int e0, int t) {
    const int c0 = ch * KC;
    const uint32_t abase = sb + (uint32_t)st * A_SIZE;
#pragma unroll
    for (int p = 0; p < 6; p++) {
        int idx = p * 512 + t;
        int plane = idx >> 10;
        int rem = idx & 1023;
        int row = rem >> 3, cb = rem & 7;
        const __half* src = &g_A[plane][0][0] + (size_t)(e0 + row) * D_ + c0 + cb * 8;
        cp16(abase + plane * A_PLANE + row * ROWB + cb * 16, src);
    }
}
__device__ __forceinline__ void load_X(uint32_t sb, int st, int ch,
                                       int i0, int b, int t,
                                       const float* __restrict__ x) {
    const int c0 = ch * KC;
    const uint32_t xbase = sb + XF32_OFF + (uint32_t)st * XF32_SZ;
    for (int idx = t; idx < 64 * 34; idx += 512) {
        int row = idx / 34, cb = idx % 34;
        int ioff = i0 + cb * 4;
        int nb = (L_ - ioff) * 4;
        nb = nb < 0 ? 0 : (nb > 16 ? 16 : nb);
        const float* src = x + ((size_t)(b * D_ + c0 + row)) * L_ + (nb > 0 ? ioff : 0);
        cp16z(xbase + row * RSF32 + cb * 16, src, nb);
    }
}
__device__ __forceinline__ void convert_X(char* smem, int k, int t) {
    const char* xf = smem + XF32_OFF + (k & 1) * XF32_SZ;
    char* xh = smem + XF16_OFF + (k & 1) * XF16_SZ;
#pragma unroll
    for (int it = 0; it < 5; it++) {
        int idx = it * 512 + t;
        if (idx < 64 * 34) {
            int row = idx / 34, c4 = idx % 34;
            float4 v = *(const float4*)(xf + row * RSF32 + c4 * 16);
            __half2 h0 = __floats2half2_rn(v.x, v.y);
            __half2 h1 = __floats2half2_rn(v.z, v.w);
            uint2 u; u.x = *(uint32_t*)&h0; u.y = *(uint32_t*)&h1;
            *(uint2*)(xh + row * ROWXB + c4 * 8) = u;
        }
    }
}

__global__ void __launch_bounds__(512, 1) gemm_kernel(const float* __restrict__ x) {
    extern __shared__ char smem[];
    const uint32_t sb = smem_u32(smem);
    const int t = threadIdx.x, wid = t >> 5, lane = t & 31;
    const int i0 = blockIdx.x * 128, e0 = blockIdx.y * 128, b = blockIdx.z;
    const int e_w = (wid & 3) * 32;
    const int i_w = (wid >> 2) * 32;

    float accE[2][4][4], accO[2][4][4];
#pragma unroll
    for (int mt = 0; mt < 2; mt++)
#pragma unroll
        for (int nt = 0; nt < 4; nt++)
#pragma unroll
            for (int j = 0; j < 4; j++) { accE[mt][nt][j] = 0.f; accO[mt][nt][j] = 0.f; }

    // prologue: A0+X0 (group), X1 (group); convert chunk 0
    load_A(sb, 0, 0, e0, t);
    load_X(sb, 0, 0, i0, b, t, x);
    CP_COMMIT();
    load_X(sb, 1, 1, i0, b, t, x);
    CP_COMMIT();
    CP_WAIT1();
    __syncthreads();
    convert_X(smem, 0, t);

    const uint32_t xRowT  = (uint32_t)((lane & 7) + ((lane >> 3) & 1) * 8) * ROWXB
                          + (uint32_t)(i_w + (lane >> 4) * 8) * 2;
    const uint32_t xRowT2 = (uint32_t)((lane & 7) + ((lane >> 3) & 1) * 8) * ROWXB
                          + (uint32_t)(i_w + 32) * 2;
    const uint32_t aRow = (uint32_t)(e_w + (lane & 15)) * ROWB + (uint32_t)(lane >> 4) * 16;
    const int srcLaneHi = (lane + 4) & 31;
    const int srcLaneLo = lane & 3;
    const bool inBody = (lane < 28);

    for (int ch = 0; ch < NCH; ++ch) {
        CP_WAIT0();
        __syncthreads();   // A(ch) + X(ch+1) arrived; h(ch) converted prev iter

        if (ch + 1 < NCH) convert_X(smem, ch + 1, t);   // overlaps with MMA below
        if (ch + 1 < NCH) { load_A(sb, (ch + 1) & 1, ch + 1, e0, t); CP_COMMIT(); }
        if (ch + 2 < NCH) { load_X(sb, ch & 1, ch + 2, i0, b, t, x); CP_COMMIT(); }

        const uint32_t sA  = sb + (uint32_t)(ch & 1) * A_SIZE;
        const uint32_t sXh = sb + XF16_OFF + (uint32_t)(ch & 1) * XF16_SZ;

#pragma unroll
        for (int kh = 0; kh < 4; ++kh) {
            const uint32_t kbA = (uint32_t)kh * 32;
            const uint32_t kbX = (uint32_t)kh * 16 * ROWXB;
            uint32_t bX[5][2], bS[4][2];
            {
                uint32_t r[4];
                ldsm_x4_t(r, sXh + xRowT + kbX);
                bX[0][0] = r[0]; bX[0][1] = r[1]; bX[1][0] = r[2]; bX[1][1] = r[3];
                ldsm_x4_t(r, sXh + xRowT + kbX + 32);
                bX[2][0] = r[0]; bX[2][1] = r[1]; bX[3][0] = r[2]; bX[3][1] = r[3];
                ldsm_x2_t(bX[4], sXh + xRowT2 + kbX);
            }
#pragma unroll
            for (int nt = 0; nt < 4; nt++)
#pragma unroll
                for (int q = 0; q < 2; q++) {
                    uint32_t hi = __shfl_sync(0xffffffffu, bX[nt][q], srcLaneHi);
                    uint32_t lo = __shfl_sync(0xffffffffu, bX[nt + 1][q], srcLaneLo);
                    bS[nt][q] = inBody ? hi : lo;
                }
#pragma unroll
            for (int s = 0; s < 3; ++s) {
                uint32_t aF[2][4];
#pragma unroll
                for (int mt = 0; mt < 2; mt++)
                    ldsm_x4(aF[mt], sA + s * A_PLANE + aRow + mt * (16 * ROWB) + kbA);
#pragma unroll
                for (int mt = 0; mt < 2; mt++)
#pragma unroll
                    for (int nt = 0; nt < 4; nt++) {
                        float* d = (s == 1) ? accE[mt][nt] : accO[mt][nt];
                        mma_fp16(d, aF[mt], (s == 2) ? bS[nt] : bX[nt]);
                    }
            }
        }
    }

    // ---- epilogue: interleave even/odd, add folded conv bias, write fp16 z ----
#pragma unroll
    for (int mt = 0; mt < 2; mt++) {
        int r0 = e0 + e_w + mt * 16 + (lane >> 2);
        float cb0 = g_cb[r0], cb1 = g_cb[r0 + 8];
#pragma unroll
        for (int nt = 0; nt < 4; nt++) {
            int ie = i0 + i_w + nt * 8 + (lane & 3) * 2;
            __half2 p0 = __floats2half2_rn(accE[mt][nt][0] + cb0, accO[mt][nt][0] + cb0);
            __half2 p1 = __floats2half2_rn(accE[mt][nt][1] + cb0, accO[mt][nt][1] + cb0);
            __half2 p2 = __floats2half2_rn(accE[mt][nt][2] + cb1, accO[mt][nt][2] + cb1);
            __half2 p3 = __floats2half2_rn(accE[mt][nt][3] + cb1, accO[mt][nt][3] + cb1);
            uint2 u0, u1;
            u0.x = *(uint32_t*)&p0; u0.y = *(uint32_t*)&p1;
            u1.x = *(uint32_t*)&p2; u1.y = *(uint32_t*)&p3;
            *(uint2*)(g_z + ((size_t)(b * D_ + r0)) * T_ + 2 * ie)     = u0;
            *(uint2*)(g_z + ((size_t)(b * D_ + r0 + 8)) * T_ + 2 * ie) = u1;
        }
    }
}

// ---------------- kernel 3: depthwise 17-tap AA, 16 outputs/thread, f32x2 ---
__device__ __forceinline__ void unp8(uint4 v, float* w) {
    const __half2* h = (const __half2*)&v;
    float2 f0 = __half22float2(h[0]);
    float2 f1 = __half22float2(h[1]);
    float2 f2 = __half22float2(h[2]);
    float2 f3 = __half22float2(h[3]);
    w[0] = f0.x; w[1] = f0.y; w[2] = f1.x; w[3] = f1.y;
    w[4] = f2.x; w[5] = f2.y; w[6] = f3.x; w[7] = f3.y;
}

__global__ __launch_bounds__(256) void aa_kernel(const float* __restrict__ aa,
                                                 const float* __restrict__ pb,
                                                 float* __restrict__ out) {
    const int row = blockIdx.x >> 1;           // b*512 + e
    const int seg = blockIdx.x & 1;
    const int t   = threadIdx.x;
    const int o0  = seg * 4096 + t * 16;
    const __half* zr = g_z + (size_t)row * T_;

    float w[32];
    if (o0 >= 8 && o0 + 24 <= T_) {
        uint4 v0 = *(const uint4*)(zr + o0 - 8);
        uint4 v1 = *(const uint4*)(zr + o0);
        uint4 v2 = *(const uint4*)(zr + o0 + 8);
        uint4 v3 = *(const uint4*)(zr + o0 + 16);
        unp8(v0, w); unp8(v1, w + 8); unp8(v2, w + 16); unp8(v3, w + 24);
    } else {
#pragma unroll
        for (int j = 0; j < 32; j++) {
            int g = o0 - 8 + j;
            w[j] = (g >= 0 && g < T_) ? __half2float(zr[g]) : 0.f;
        }
    }

    float kc[KS];
#pragma unroll
    for (int j = 0; j < KS; j++) kc[j] = __ldg(&aa[j]);
    float bias = __ldg(&pb[row & (D_ - 1)]);

    unsigned long long E[16], O[15], acc[8];
#pragma unroll
    for (int m = 0; m < 16; m++) E[m] = pack2(w[2 * m], w[2 * m + 1]);
#pragma unroll
    for (int m = 0; m < 15; m++) O[m] = pack2(w[2 * m + 1], w[2 * m + 2]);
    unsigned long long b2 = pack2(bias, bias);
#pragma unroll
    for (int p = 0; p < 8; p++) acc[p] = b2;

#pragma unroll
    for (int j = 0; j < KS; j++) {
        unsigned long long k2 = pack2(kc[j], kc[j]);
        const unsigned long long* src = (j & 1) ? &O[j >> 1] : &E[j >> 1];
#pragma unroll
        for (int p = 0; p < 8; p++) acc[p] = fma2(k2, src[p], acc[p]);
    }

    float* op = out + (size_t)row * T_ + o0;
#pragma unroll
    for (int q = 0; q < 4; q++) {
        float2 a0 = unpack2(acc[2 * q]);
        float2 a1 = unpack2(acc[2 * q + 1]);
        float4 v; v.x = a0.x; v.y = a0.y; v.z = a1.x; v.w = a1.y;
        *(float4*)&op[q * 4] = v;
    }
}

// ---------------- launch ----------------
extern "C" void kernel_launch(void* const* d_in, const int* in_sizes, int n_in,
                              void* d_out, int out_size) {
    const float* x      = (const float*)d_in[0];
    const float* conv_w = (const float*)d_in[1];
    const float* conv_b = (const float*)d_in[2];
    const float* aa_k   = (const float*)d_in[3];
    const float* proj_w = (const float*)d_in[4];
    const float* proj_b = (const float*)d_in[5];
    float* out = (float*)d_out;

    cudaFuncSetAttribute(gemm_kernel, cudaFuncAttributeMaxDynamicSharedMemorySize, GEMM_SMEM);

    prep_kernel<<<dim3(PREP_GRID), 256>>>(conv_w, conv_b, proj_w);
    gemm_kernel<<<dim3(L_ / 128, D_ / 128, B_), 512, GEMM_SMEM>>>(x);
    aa_kernel<<<dim3(B_ * D_ * 2), 256>>>(aa_k, proj_b, out);
}